// round 4
// baseline (speedup 1.0000x reference)
#include <cuda_runtime.h>
#include <math.h>

#define BSZ 256
#define HSZ 256
#define TIN 336
#define TOUT 96
#define FSZ 32

// ---------------- device-global scratch (allocation-free) ----------------
__device__ float g_h0[2][BSZ * HSZ];
__device__ float g_c0[BSZ * HSZ];
__device__ float g_h1[2][BSZ * HSZ];
__device__ float g_c1[BSZ * HSZ];
__device__ float g_Wp[4 * HSZ * HSZ];   // dec_Wih0 @ dec_Wout  [1024 x 256]
__device__ float g_bp[4 * HSZ];         // dec_b0 + dec_Wih0 @ dec_bout
__device__ float g_h1s[(size_t)TOUT * BSZ * HSZ]; // decoder h1 per step (25MB)

// ---------------- init / precompute kernels ----------------
__global__ void zero_init_kernel() {
  int i = blockIdx.x * blockDim.x + threadIdx.x;
  g_h0[0][i] = 0.f;
  g_c0[i] = 0.f;
  g_h1[0][i] = 0.f;
  g_c1[i] = 0.f;
}

__global__ void wp_kernel(const float* __restrict__ Wih0,
                          const float* __restrict__ Wout) {
  __shared__ float wr[FSZ];
  int c = blockIdx.x;                    // gate row 0..1023
  if (threadIdx.x < FSZ) wr[threadIdx.x] = Wih0[c * FSZ + threadIdx.x];
  __syncthreads();
  int k = threadIdx.x;                   // hidden col 0..255
  float acc = 0.f;
#pragma unroll
  for (int f = 0; f < FSZ; ++f) acc += wr[f] * Wout[f * HSZ + k];
  g_Wp[c * HSZ + k] = acc;
}

__global__ void bp_kernel(const float* __restrict__ Wih0,
                          const float* __restrict__ b0,
                          const float* __restrict__ bout) {
  int c = blockIdx.x * blockDim.x + threadIdx.x;
  float acc = b0[c];
#pragma unroll
  for (int f = 0; f < FSZ; ++f) acc += Wih0[c * FSZ + f] * bout[f];
  g_bp[c] = acc;
}

// ---------------- fused LSTM cell step ----------------
// gates[B,4H] = A[B,D] @ Wih^T + hin[B,H] @ Whh^T + bias
// c' = sig(f)*c + sig(i)*tanh(g);  h' = sig(o)*tanh(c')
// Tile: 32 batch rows x 16 hidden units (=64 gate cols: i/f/g/o groups).
// Grid (8, 16) = 128 CTAs, 256 threads, each thread 2x4 outputs.
__global__ __launch_bounds__(256) void lstm_step(
    const float* __restrict__ A, int lda, int D,
    const float* __restrict__ Wih, int ldwi,
    const float* __restrict__ hin,
    const float* __restrict__ Whh,
    const float* __restrict__ bias,
    float* __restrict__ c_state,
    float* __restrict__ h_out,
    float* __restrict__ h_out2) {
  __shared__ float sm[32 * 34 + 32 * 68];   // As[k][m] pitch34, Ws[k][n] pitch68
  float* As = sm;
  float* Ws = sm + 32 * 34;

  int tid = threadIdx.x;
  int row0 = blockIdx.x * 32;
  int hbase = blockIdx.y * 16;
  int txc = tid & 15;        // 16 col-groups (4 cols each)
  int txr = tid >> 4;        // 16 row-groups (2 rows each)
  float acc[2][4] = {};

  for (int seg = 0; seg < 2; ++seg) {
    const float* Ap = seg ? hin : A;
    int ld = seg ? HSZ : lda;
    int K = seg ? HSZ : D;
    const float* Wb = seg ? Whh : Wih;
    int ldw = seg ? HSZ : ldwi;

    for (int k0 = 0; k0 < K; k0 += 32) {
      __syncthreads();
      {  // A tile: 32 rows x 32 k, transposed into As[k][m]
        int arow = tid >> 3, akq = tid & 7;
        float4 v = *(const float4*)(Ap + (size_t)(row0 + arow) * ld + k0 + akq * 4);
        As[(akq * 4 + 0) * 34 + arow] = v.x;
        As[(akq * 4 + 1) * 34 + arow] = v.y;
        As[(akq * 4 + 2) * 34 + arow] = v.z;
        As[(akq * 4 + 3) * 34 + arow] = v.w;
      }
#pragma unroll
      for (int q = 0; q < 2; ++q) {  // W tile: 64 gate cols x 32 k -> Ws[k][n]
        int idx = tid + q * 256;
        int wn = idx >> 3, wkq = idx & 7;
        int grow = (wn >> 4) * HSZ + hbase + (wn & 15);
        float4 v = *(const float4*)(Wb + (size_t)grow * ldw + k0 + wkq * 4);
        Ws[(wkq * 4 + 0) * 68 + wn] = v.x;
        Ws[(wkq * 4 + 1) * 68 + wn] = v.y;
        Ws[(wkq * 4 + 2) * 68 + wn] = v.z;
        Ws[(wkq * 4 + 3) * 68 + wn] = v.w;
      }
      __syncthreads();
#pragma unroll
      for (int k = 0; k < 32; ++k) {
        float2 a = *(const float2*)&As[k * 34 + 2 * txr];
        float4 w = *(const float4*)&Ws[k * 68 + 4 * txc];
        acc[0][0] += a.x * w.x; acc[0][1] += a.x * w.y;
        acc[0][2] += a.x * w.z; acc[0][3] += a.x * w.w;
        acc[1][0] += a.y * w.x; acc[1][1] += a.y * w.y;
        acc[1][2] += a.y * w.z; acc[1][3] += a.y * w.w;
      }
    }
  }

  // exchange gates through SMEM so each thread sees all 4 gates of its cells
  __syncthreads();
  float* gsm = sm;  // [32][64]
#pragma unroll
  for (int i = 0; i < 2; ++i)
#pragma unroll
    for (int j = 0; j < 4; ++j)
      gsm[(2 * txr + i) * 64 + 4 * txc + j] = acc[i][j];
  __syncthreads();

#pragma unroll
  for (int q = 0; q < 2; ++q) {
    int e = tid + q * 256;      // 512 cells in tile
    int r = e >> 4, hid = e & 15;
    int gb = row0 + r, gh = hbase + hid;
    float gi = gsm[r * 64 + hid]      + bias[0 * HSZ + gh];
    float gf = gsm[r * 64 + 16 + hid] + bias[1 * HSZ + gh];
    float gg = gsm[r * 64 + 32 + hid] + bias[2 * HSZ + gh];
    float go = gsm[r * 64 + 48 + hid] + bias[3 * HSZ + gh];
    float c = c_state[gb * HSZ + gh];
    float si = 1.f / (1.f + expf(-gi));
    float sf = 1.f / (1.f + expf(-gf));
    float so = 1.f / (1.f + expf(-go));
    float cn = sf * c + si * tanhf(gg);
    float hn = so * tanhf(cn);
    c_state[gb * HSZ + gh] = cn;
    h_out[gb * HSZ + gh] = hn;
    if (h_out2) h_out2[gb * HSZ + gh] = hn;
  }
}

// ---------------- final projection: out[b,s,f] = h1s[s][b,:] . Wout[f,:] + bout[f]
__global__ __launch_bounds__(256) void out_proj(const float* __restrict__ Wout,
                                                const float* __restrict__ bout,
                                                float* __restrict__ out) {
  __shared__ float hs[32][65];
  __shared__ float wsT[64][36];
  int tid = threadIdx.x;
  int b0 = blockIdx.x * 32;
  int s = blockIdx.y;
  int bloc = tid & 31;
  int f0 = (tid >> 5) * 4;
  float acc[4] = {0.f, 0.f, 0.f, 0.f};
  const float* hsrc = g_h1s + (size_t)s * BSZ * HSZ;

  for (int k0 = 0; k0 < HSZ; k0 += 64) {
    __syncthreads();
#pragma unroll
    for (int q = 0; q < 2; ++q) {
      int idx = tid + q * 256;
      int row = idx >> 4, kq = idx & 15;
      float4 v = *(const float4*)(hsrc + (size_t)(b0 + row) * HSZ + k0 + kq * 4);
      hs[row][kq * 4 + 0] = v.x; hs[row][kq * 4 + 1] = v.y;
      hs[row][kq * 4 + 2] = v.z; hs[row][kq * 4 + 3] = v.w;
      float4 w = *(const float4*)(Wout + (size_t)row * HSZ + k0 + kq * 4);
      wsT[kq * 4 + 0][row] = w.x; wsT[kq * 4 + 1][row] = w.y;
      wsT[kq * 4 + 2][row] = w.z; wsT[kq * 4 + 3][row] = w.w;
    }
    __syncthreads();
#pragma unroll 8
    for (int kk = 0; kk < 64; ++kk) {
      float hv = hs[bloc][kk];
      float4 w = *(const float4*)&wsT[kk][f0];
      acc[0] += hv * w.x; acc[1] += hv * w.y;
      acc[2] += hv * w.z; acc[3] += hv * w.w;
    }
  }
  float* op = out + (size_t)(b0 + bloc) * TOUT * FSZ + s * FSZ + f0;
  op[0] = acc[0] + bout[f0 + 0];
  op[1] = acc[1] + bout[f0 + 1];
  op[2] = acc[2] + bout[f0 + 2];
  op[3] = acc[3] + bout[f0 + 3];
}

// ---------------- host ----------------
static float* sym_addr(const void* sym) {
  void* p = nullptr;
  cudaGetSymbolAddress(&p, sym);
  return (float*)p;
}

extern "C" void kernel_launch(void* const* d_in, const int* in_sizes, int n_in,
                              void* d_out, int out_size) {
  (void)in_sizes; (void)n_in; (void)out_size;
  const float* x     = (const float*)d_in[0];
  const float* eWih0 = (const float*)d_in[1];
  const float* eWhh0 = (const float*)d_in[2];
  const float* eb0   = (const float*)d_in[3];
  const float* eWih1 = (const float*)d_in[4];
  const float* eWhh1 = (const float*)d_in[5];
  const float* eb1   = (const float*)d_in[6];
  const float* dWih0 = (const float*)d_in[7];
  const float* dWhh0 = (const float*)d_in[8];
  const float* db0   = (const float*)d_in[9];
  const float* dWih1 = (const float*)d_in[10];
  const float* dWhh1 = (const float*)d_in[11];
  const float* db1   = (const float*)d_in[12];
  const float* dWout = (const float*)d_in[13];
  const float* dbout = (const float*)d_in[14];

  float* h0  = sym_addr(g_h0);
  float* c0  = sym_addr(g_c0);
  float* h1  = sym_addr(g_h1);
  float* c1  = sym_addr(g_c1);
  float* Wp  = sym_addr(g_Wp);
  float* bp  = sym_addr(g_bp);
  float* h1s = sym_addr(g_h1s);

  const int pN = BSZ * HSZ;
  dim3 grid(BSZ / 32, HSZ / 16);

  zero_init_kernel<<<(BSZ * HSZ) / 256, 256>>>();
  wp_kernel<<<4 * HSZ, 256>>>(dWih0, dWout);
  bp_kernel<<<(4 * HSZ) / 256, 256>>>(dWih0, db0, dbout);

  int par = 0;
  // -------- encoder --------
  for (int t = 0; t < TIN; ++t) {
    lstm_step<<<grid, 256>>>(x + (size_t)t * FSZ, TIN * FSZ, FSZ,
                             eWih0, FSZ,
                             h0 + par * pN, eWhh0, eb0,
                             c0, h0 + (par ^ 1) * pN, nullptr);
    lstm_step<<<grid, 256>>>(h0 + (par ^ 1) * pN, HSZ, HSZ,
                             eWih1, HSZ,
                             h1 + par * pN, eWhh1, eb1,
                             c1, h1 + (par ^ 1) * pN, nullptr);
    par ^= 1;
  }
  // -------- decoder --------
  for (int s = 0; s < TOUT; ++s) {
    if (s == 0) {
      // y0 = x[:, -1, :] feeds original dec_Wih0
      lstm_step<<<grid, 256>>>(x + (size_t)(TIN - 1) * FSZ, TIN * FSZ, FSZ,
                               dWih0, FSZ,
                               h0 + par * pN, dWhh0, db0,
                               c0, h0 + (par ^ 1) * pN, nullptr);
    } else {
      // y = h1@Wout^T + bout folded into W' = Wih0@Wout, b' = b0 + Wih0@bout
      lstm_step<<<grid, 256>>>(h1 + par * pN, HSZ, HSZ,
                               Wp, HSZ,
                               h0 + par * pN, dWhh0, bp,
                               c0, h0 + (par ^ 1) * pN, nullptr);
    }
    lstm_step<<<grid, 256>>>(h0 + (par ^ 1) * pN, HSZ, HSZ,
                             dWih1, HSZ,
                             h1 + par * pN, dWhh1, db1,
                             c1, h1 + (par ^ 1) * pN,
                             h1s + (size_t)s * pN);
    par ^= 1;
  }
  // -------- output projection for all 96 steps --------
  out_proj<<<dim3(BSZ / 32, TOUT), 256>>>(dWout, dbout, (float*)d_out);
}